// round 14
// baseline (speedup 1.0000x reference)
#include <cuda_runtime.h>
#include <cuda_bf16.h>

// Problem constants
#define TT    256
#define BB    1000
#define DD    300
#define H4    8
#define NCONS 8                   // consumer blocks (first 8 of grid)
#define NT_PER_T 4                // tiles per timestep (4 x 256 rows)
#define NPROD (TT * NT_PER_T)     // 1024 producer blocks

// padded W smem: per d4-group (4 d x 8 g = 32 floats) in 36-float slot
#define WSLOT 36
#define WP_FLOATS (75 * WSLOT)    // 2700

__device__ float g_xg[TT * BB * H4];   // xg[t][b][g]  (8.192 MB)
__device__ int   g_cnt[TT];            // tiles completed per timestep

// ---------------- helpers ----------------
__device__ __forceinline__ void fma2(unsigned long long& acc,
                                     unsigned long long a,
                                     unsigned long long b) {
    asm volatile("fma.rn.f32x2 %0, %1, %2, %3;" : "=l"(acc) : "l"(a), "l"(b), "l"(acc));
}
__device__ __forceinline__ unsigned long long add2(unsigned long long a,
                                                   unsigned long long b) {
    unsigned long long r;
    asm("add.rn.f32x2 %0, %1, %2;" : "=l"(r) : "l"(a), "l"(b));
    return r;
}
__device__ __forceinline__ unsigned long long pack2(float x) {
    unsigned long long r;
    asm("mov.b64 %0, {%1, %1};" : "=l"(r) : "r"(__float_as_uint(x)));
    return r;
}
__device__ __forceinline__ void unpack2(unsigned long long p, float& lo, float& hi) {
    unsigned a, b;
    asm("mov.b64 {%0, %1}, %2;" : "=r"(a), "=r"(b) : "l"(p));
    lo = __uint_as_float(a);
    hi = __uint_as_float(b);
}

__device__ __forceinline__ int ld_acquire(const int* p) {
    unsigned v;
    asm volatile("ld.acquire.gpu.global.u32 %0, [%1];" : "=r"(v) : "l"(p) : "memory");
    return (int)v;
}
__device__ __forceinline__ void wait_cnt(int t) {
    if (ld_acquire(&g_cnt[t]) >= NT_PER_T) return;
    for (;;) {
        if (ld_acquire(&g_cnt[t]) >= NT_PER_T) return;
        __nanosleep(64);
    }
}

// fast activations via MUFU.TANH (validated: rel_err ~1e-7 in R10-R13)
__device__ __forceinline__ float tanh_fast(float x) {
    float r;
    asm("tanh.approx.f32 %0, %1;" : "=f"(r) : "f"(x));
    return r;
}
__device__ __forceinline__ float sig_fast(float x) {
    return fmaf(tanh_fast(0.5f * x), 0.5f, 0.5f);
}

__global__ void reset_kernel() {
    g_cnt[threadIdx.x] = 0;
}

__global__ __launch_bounds__(256, 3) void fused_kernel(
    const float* __restrict__ x,      // [T,B,300]
    const float* __restrict__ Wih0,   // [8,300]
    const float* __restrict__ bih0,
    const float* __restrict__ bhh0,
    const float* __restrict__ h0in,   // [2,B,2]
    const float* __restrict__ c0in,
    const float* __restrict__ Whh0,   // [8,2]
    const float* __restrict__ Wih1,   // [8,2]
    const float* __restrict__ Whh1,   // [8,2]
    const float* __restrict__ bih1,
    const float* __restrict__ bhh1,
    const float* __restrict__ Wlin,   // [1,2]
    const float* __restrict__ blin,
    float* __restrict__ out)          // [B]
{
    __shared__ float sWp[WP_FLOATS];  // producer: padded W
    __shared__ float sB[H4];
    __shared__ float sCW[4 * 16];     // consumer: A0,A1,C0,C1 by [kind][layer*8+g]

    const int bid = blockIdx.x;
    const int tid = threadIdx.x;

    if (bid >= NCONS) {
        // ============ PRODUCER: 256-row tile, 4 rows/thread ==================
        const int pid = bid - NCONS;
        const int t   = pid >> 2;
        const int s   = pid & 3;
        const int r0  = s * 256;           // 0,256,512,768

        for (int i = tid; i < 75 * 32; i += 256) {
            int d4  = i >> 5;
            int rem = i & 31;
            int j   = rem >> 3, g = rem & 7;
            sWp[d4 * WSLOT + j * 8 + g] = Wih0[g * DD + d4 * 4 + j];
        }
        if (tid < H4) sB[tid] = bih0[tid] + bhh0[tid];
        __syncthreads();

        const int lane = tid & 31;
        const int warp = tid >> 5;
        const int r8   = lane >> 2;
        const int c    = lane & 3;

        // this thread's 4 rows (tile-local): r0 + warp*32 + k*8 + r8
        int   grow[4];
        bool  valid[4];
        const float4* xrow[4];
        #pragma unroll
        for (int k = 0; k < 4; k++) {
            grow[k]  = r0 + warp * 32 + k * 8 + r8;
            valid[k] = (grow[k] < BB);
            const int rsafe = valid[k] ? grow[k] : 0;
            xrow[k] = reinterpret_cast<const float4*>(x + ((size_t)t * BB + rsafe) * DD);
        }

        unsigned long long acc[4][4];
        #pragma unroll
        for (int k = 0; k < 4; k++)
            #pragma unroll
            for (int a = 0; a < 4; a++)
                acc[k][a] = 0ull;

        #pragma unroll
        for (int i = 0; i < 19; i++) {
            const int d4 = i * 4 + c;
            if (d4 < 75) {
                float4 v[4];
                #pragma unroll
                for (int k = 0; k < 4; k++)
                    if (valid[k]) v[k] = xrow[k][d4];

                const float* wbp = &sWp[d4 * WSLOT];
                #pragma unroll
                for (int j = 0; j < 4; j++) {
                    ulonglong2 wA = *reinterpret_cast<const ulonglong2*>(wbp + j * 8);
                    ulonglong2 wB = *reinterpret_cast<const ulonglong2*>(wbp + j * 8 + 4);
                    #pragma unroll
                    for (int k = 0; k < 4; k++) {
                        const float xs = (j == 0) ? v[k].x : (j == 1) ? v[k].y
                                       : (j == 2) ? v[k].z : v[k].w;
                        unsigned long long xp = pack2(xs);
                        fma2(acc[k][0], xp, wA.x);
                        fma2(acc[k][1], xp, wA.y);
                        fma2(acc[k][2], xp, wB.x);
                        fma2(acc[k][3], xp, wB.y);
                    }
                }
            }
        }

        // reduce across the 4 c-lanes; add bias; store
        ulonglong2 b01 = *reinterpret_cast<const ulonglong2*>(&sB[0]);
        ulonglong2 b23 = *reinterpret_cast<const ulonglong2*>(&sB[4]);
        #pragma unroll
        for (int k = 0; k < 4; k++) {
            unsigned long long a0 = acc[k][0], a1 = acc[k][1];
            unsigned long long a2 = acc[k][2], a3 = acc[k][3];
            a0 = add2(a0, __shfl_xor_sync(0xffffffffu, a0, 1));
            a1 = add2(a1, __shfl_xor_sync(0xffffffffu, a1, 1));
            a2 = add2(a2, __shfl_xor_sync(0xffffffffu, a2, 1));
            a3 = add2(a3, __shfl_xor_sync(0xffffffffu, a3, 1));
            a0 = add2(a0, __shfl_xor_sync(0xffffffffu, a0, 2));
            a1 = add2(a1, __shfl_xor_sync(0xffffffffu, a1, 2));
            a2 = add2(a2, __shfl_xor_sync(0xffffffffu, a2, 2));
            a3 = add2(a3, __shfl_xor_sync(0xffffffffu, a3, 2));

            if (c == 0 && valid[k]) {
                a0 = add2(a0, b01.x);
                a1 = add2(a1, b01.y);
                a2 = add2(a2, b23.x);
                a3 = add2(a3, b23.y);
                float4 o0, o1;
                unpack2(a0, o0.x, o0.y);
                unpack2(a1, o0.z, o0.w);
                unpack2(a2, o1.x, o1.y);
                unpack2(a3, o1.z, o1.w);
                const int row = t * BB + grow[k];
                float4* dst = reinterpret_cast<float4*>(&g_xg[(size_t)row * H4]);
                dst[0] = o0;
                dst[1] = o1;
            }
        }
        __threadfence();
        __syncthreads();
        if (tid == 0) atomicAdd(&g_cnt[t], 1);
        return;
    }

    // ============ CONSUMER (R13 verbatim; flag threshold = 4) ================
    if (tid < 16) {
        const int l = tid >> 3, g = tid & 7;
        sCW[0 * 16 + tid] = l ? __ldg(&Whh1[g * 2 + 0]) : __ldg(&Whh0[g * 2 + 0]);
        sCW[1 * 16 + tid] = l ? __ldg(&Whh1[g * 2 + 1]) : __ldg(&Whh0[g * 2 + 1]);
        sCW[2 * 16 + tid] = l ? __ldg(&Wih1[g * 2 + 0]) : 0.0f;
        sCW[3 * 16 + tid] = l ? __ldg(&Wih1[g * 2 + 1]) : 0.0f;
    }
    __syncthreads();
    volatile const float* vw = sCW;

    const int warp = tid >> 5;
    const int lane = tid & 31;
    const bool l1  = (lane >= 16);
    const int wb   = l1 ? 8 : 0;
    const int e    = (bid * 8 + warp) * 16 + (lane & 15);   // 0..1023
    const int b    = (e < BB) ? e : (BB - 1);

    float ha, hb, ca, cb;
    float hpa = 0.0f, hpb = 0.0f;
    float vb[H4];   // l0: per-step xg; l1: constant bias

    if (!l1) {
        #pragma unroll
        for (int g = 0; g < H4; g++) vb[g] = 0.0f;
        ha = h0in[b * 2 + 0]; hb = h0in[b * 2 + 1];
        ca = c0in[b * 2 + 0]; cb = c0in[b * 2 + 1];
    } else {
        #pragma unroll
        for (int g = 0; g < H4; g++) vb[g] = __ldg(&bih1[g]) + __ldg(&bhh1[g]);
        ha = h0in[BB * 2 + b * 2 + 0]; hb = h0in[BB * 2 + b * 2 + 1];
        ca = c0in[BB * 2 + b * 2 + 0]; cb = c0in[BB * 2 + b * 2 + 1];
    }
    const float wl0 = __ldg(&Wlin[0]), wl1 = __ldg(&Wlin[1]), bl = __ldg(&blin[0]);

    const float4* xg4 = reinterpret_cast<const float4*>(g_xg);
    const int idx0 = b * 2;
    const int ST   = BB * 2;   // float4 stride per timestep

    float4 r0[4], r1[4];
    #pragma unroll
    for (int d = 0; d < 4; d++) {
        wait_cnt(d);
        if (!l1) {
            r0[d] = __ldg(&xg4[idx0 + d * ST]);
            r1[d] = __ldg(&xg4[idx0 + d * ST + 1]);
        }
    }

    #pragma unroll 1
    for (int s4 = 0; s4 < TT / 4; s4++) {
        #pragma unroll
        for (int u = 0; u < 4; u++) {
            const int s = s4 * 4 + u;

            if (!l1) {
                vb[0] = r0[u].x; vb[1] = r0[u].y; vb[2] = r0[u].z; vb[3] = r0[u].w;
                vb[4] = r1[u].x; vb[5] = r1[u].y; vb[6] = r1[u].z; vb[7] = r1[u].w;
            }
            if (s + 4 < TT) {
                wait_cnt(s + 4);
                if (!l1) {
                    r0[u] = __ldg(&xg4[idx0 + (s + 4) * ST]);
                    r1[u] = __ldg(&xg4[idx0 + (s + 4) * ST + 1]);
                }
            }

            float pre[H4];
            #pragma unroll
            for (int g = 0; g < H4; g++) {
                float base = fmaf(vw[2 * 16 + wb + g], hpa,
                             fmaf(vw[3 * 16 + wb + g], hpb, vb[g]));
                pre[g] = fmaf(vw[0 * 16 + wb + g], ha,
                         fmaf(vw[1 * 16 + wb + g], hb, base));
            }

            float i0 = sig_fast(pre[0]),  i1 = sig_fast(pre[1]);
            float f0 = sig_fast(pre[2]),  f1 = sig_fast(pre[3]);
            float g0 = tanh_fast(pre[4]), g1 = tanh_fast(pre[5]);
            float o0 = sig_fast(pre[6]),  o1 = sig_fast(pre[7]);
            float nca = fmaf(f0, ca, i0 * g0);
            float ncb = fmaf(f1, cb, i1 * g1);
            float nha = o0 * tanh_fast(nca);
            float nhb = o1 * tanh_fast(ncb);

            const bool valid = l1 ? (s >= 1) : true;
            if (valid) { ca = nca; cb = ncb; ha = nha; hb = nhb; }

            hpa = __shfl_up_sync(0xffffffffu, ha, 16);
            hpb = __shfl_up_sync(0xffffffffu, hb, 16);
        }
    }

    // epilogue step s = TT
    {
        float pre[H4];
        #pragma unroll
        for (int g = 0; g < H4; g++) {
            float base = fmaf(vw[2 * 16 + wb + g], hpa,
                         fmaf(vw[3 * 16 + wb + g], hpb, vb[g]));
            pre[g] = fmaf(vw[0 * 16 + wb + g], ha,
                     fmaf(vw[1 * 16 + wb + g], hb, base));
        }
        float i0 = sig_fast(pre[0]),  i1 = sig_fast(pre[1]);
        float f0 = sig_fast(pre[2]),  f1 = sig_fast(pre[3]);
        float g0 = tanh_fast(pre[4]), g1 = tanh_fast(pre[5]);
        float o0 = sig_fast(pre[6]),  o1 = sig_fast(pre[7]);
        float nca = fmaf(f0, ca, i0 * g0);
        float ncb = fmaf(f1, cb, i1 * g1);
        float nha = o0 * tanh_fast(nca);
        float nhb = o1 * tanh_fast(ncb);
        if (l1) { ca = nca; cb = ncb; ha = nha; hb = nhb; }
    }

    if (l1 && e < BB)
        out[b] = fmaf(wl0, ha, fmaf(wl1, hb, bl));
}

// ---------------------------------------------------------------------------
extern "C" void kernel_launch(void* const* d_in, const int* in_sizes, int n_in,
                              void* d_out, int out_size)
{
    const float* x     = (const float*)d_in[0];
    const float* h0    = (const float*)d_in[1];
    const float* c0    = (const float*)d_in[2];
    const float* Wih0  = (const float*)d_in[3];
    const float* Whh0  = (const float*)d_in[4];
    const float* bih0  = (const float*)d_in[5];
    const float* bhh0  = (const float*)d_in[6];
    const float* Wih1  = (const float*)d_in[7];
    const float* Whh1  = (const float*)d_in[8];
    const float* bih1  = (const float*)d_in[9];
    const float* bhh1  = (const float*)d_in[10];
    const float* Wlin  = (const float*)d_in[11];
    const float* blin  = (const float*)d_in[12];
    float* out = (float*)d_out;

    reset_kernel<<<1, TT>>>();
    fused_kernel<<<NCONS + NPROD, 256>>>(
        x, Wih0, bih0, bhh0,
        h0, c0, Whh0, Wih1, Whh1, bih1, bhh1, Wlin, blin,
        out);
}